// round 14
// baseline (speedup 1.0000x reference)
#include <cuda_runtime.h>
#include <cuda_fp16.h>
#include <math.h>
#include <stdint.h>

#define TWO_N 8192
#define DDIM  256
#define NHALF 4096
#define BM    128
#define NBJ   64
#define NTILE (NBJ * (NBJ + 1) / 2)   /* 2080 lower-triangle pairs */
#define MARGIN 0.5f
#define NCHUNK 8                       /* 8 chunks of K=32 */
#define NSTAGE 5
#define ROWB   80                      /* smem row stride bytes (32 halfs + 8 pad) */
#define STAGEB (BM * ROWB)             /* 10240 B per (A or B) stage */
#define NBLK1  16                      /* stage-1 reduction blocks */

/* dynamic smem layout (bytes) */
#define OFF_MROW    (NSTAGE * 2 * STAGEB)          /* 102400: row-rect mask 2KB */
#define OFF_MCOL    (OFF_MROW + 2048)              /* col-rect mask 2KB */
#define OFF_SY2A    (OFF_MCOL + 2048)
#define OFF_SY2B    (OFF_SY2A + 512)
#define OFF_ROWRED  (OFF_SY2B + 512)               /* 128*2 floats */
#define OFF_COLRED  (OFF_ROWRED + 1024)            /* 128*4 floats */
#define SMEM_TOTAL  (OFF_COLRED + 2048)            /* 110592 B */

// ------------------------- device scratch (no allocs allowed) --------------
__device__ float    g_sqnorm[TWO_N];
__device__ float    g_partial[NBJ * TWO_N];
__device__ float    g_ap[NHALF];
__device__ int      g_mask_mode;   // 0=int32 1=uint8 2=float32 3=bf16
__device__ __half   g_eh[TWO_N * DDIM];                 // 4 MB fp16 embeddings
__device__ float    g_bsum[NBLK1];
__device__ int      g_bcnt[NBLK1];

// ------------------------- helpers -----------------------------------------
__device__ __forceinline__ uint32_t smem_u32(const void* p) {
    uint32_t a;
    asm("{ .reg .u64 t; cvta.to.shared.u64 t, %1; cvt.u32.u64 %0, t; }"
        : "=r"(a) : "l"(p));
    return a;
}
__device__ __forceinline__ void cpa16(uint32_t dst, const void* src) {
    asm volatile("cp.async.cg.shared.global [%0], [%1], 16;" :: "r"(dst), "l"(src));
}
__device__ __forceinline__ void cpa_commit() {
    asm volatile("cp.async.commit_group;" ::: "memory");
}
template <int N>
__device__ __forceinline__ void cpa_wait() {
    asm volatile("cp.async.wait_group %0;" :: "n"(N) : "memory");
}
__device__ __forceinline__ void ldmx4(uint32_t* r, uint32_t addr) {
    asm volatile("ldmatrix.sync.aligned.m8n8.x4.shared.b16 {%0,%1,%2,%3}, [%4];"
                 : "=r"(r[0]), "=r"(r[1]), "=r"(r[2]), "=r"(r[3]) : "r"(addr));
}
__device__ __forceinline__ void mma16816(float* c, const uint32_t* a, const uint32_t* b) {
    asm volatile(
        "mma.sync.aligned.m16n8k16.row.col.f32.f16.f16.f32 "
        "{%0,%1,%2,%3}, {%4,%5,%6,%7}, {%8,%9}, {%0,%1,%2,%3};"
        : "+f"(c[0]), "+f"(c[1]), "+f"(c[2]), "+f"(c[3])
        : "r"(a[0]), "r"(a[1]), "r"(a[2]), "r"(a[3]), "r"(b[0]), "r"(b[1]));
}

// ------------------------- prep: detect + sqnorm + fp16 convert -------------
__global__ void prep_kernel(const float* __restrict__ E,
                            const unsigned int* __restrict__ mraw) {
    if (blockIdx.x == 0) {
        __shared__ int has_gt1, has_f32one, has_bf16pat;
        if (threadIdx.x == 0) { has_gt1 = 0; has_f32one = 0; has_bf16pat = 0; }
        __syncthreads();
        for (int i = threadIdx.x; i < 1024; i += blockDim.x) {
            unsigned int w = mraw[i];
            if (w == 0x3F803F80u || w == 0x00003F80u) atomicOr(&has_bf16pat, 1);
            else if (w == 0x3F800000u)                atomicOr(&has_f32one, 1);
            else if (w > 1u)                          atomicOr(&has_gt1, 1);
        }
        __syncthreads();
        if (threadIdx.x == 0) {
            int mode;
            if (has_bf16pat)      mode = 3;
            else if (has_f32one)  mode = 2;
            else if (has_gt1)     mode = 1;
            else                  mode = 0;
            g_mask_mode = mode;
        }
    }

    int warp = (blockIdx.x * blockDim.x + threadIdx.x) >> 5;
    int lane = threadIdx.x & 31;
    if (warp >= TWO_N) return;
    const float* row = E + (size_t)warp * DDIM;
    float4 v0 = ((const float4*)row)[lane * 2];
    float4 v1 = ((const float4*)row)[lane * 2 + 1];
    float s = v0.x * v0.x;
    s = fmaf(v0.y, v0.y, s); s = fmaf(v0.z, v0.z, s); s = fmaf(v0.w, v0.w, s);
    s = fmaf(v1.x, v1.x, s); s = fmaf(v1.y, v1.y, s);
    s = fmaf(v1.z, v1.z, s); s = fmaf(v1.w, v1.w, s);
    __half2 h[4];
    h[0] = __floats2half2_rn(v0.x, v0.y);
    h[1] = __floats2half2_rn(v0.z, v0.w);
    h[2] = __floats2half2_rn(v1.x, v1.y);
    h[3] = __floats2half2_rn(v1.z, v1.w);
    *(uint4*)(g_eh + (size_t)warp * DDIM + lane * 8) = *(uint4*)h;
#pragma unroll
    for (int o = 16; o > 0; o >>= 1) s += __shfl_xor_sync(0xffffffffu, s, o);
    if (lane == 0) g_sqnorm[warp] = s;
}

// ------------------------- per-tile mask packing into smem ------------------
__device__ __forceinline__ void pack_rect(const void* __restrict__ mraw, int mode,
                                          int rowbase, int colbase,
                                          uint32_t* __restrict__ dst, int tid) {
#pragma unroll
    for (int w = tid; w < 512; w += 256) {
        int rr = w >> 2, wq = w & 3;
        size_t ebase = (size_t)(rowbase + rr) * TWO_N + colbase + wq * 32;
        uint32_t bits = 0u;
        if (mode == 0 || mode == 2) {              // int32 / float32 (4 B/elem)
            const uint4* p = (const uint4*)mraw + (ebase >> 2);
            uint32_t vm = (mode == 2) ? 0x7fffffffu : 0xffffffffu;
#pragma unroll
            for (int q = 0; q < 8; q++) {
                uint4 v = p[q];
                bits |= ((uint32_t)((v.x & vm) != 0u)) << (q * 4 + 0);
                bits |= ((uint32_t)((v.y & vm) != 0u)) << (q * 4 + 1);
                bits |= ((uint32_t)((v.z & vm) != 0u)) << (q * 4 + 2);
                bits |= ((uint32_t)((v.w & vm) != 0u)) << (q * 4 + 3);
            }
        } else if (mode == 1) {                    // uint8
            const uint4* p = (const uint4*)mraw + (ebase >> 4);
#pragma unroll
            for (int q = 0; q < 2; q++) {
                uint4 v = p[q];
                uint32_t ws[4] = {v.x, v.y, v.z, v.w};
#pragma unroll
                for (int k = 0; k < 4; k++)
#pragma unroll
                    for (int b = 0; b < 4; b++)
                        bits |= ((uint32_t)(((ws[k] >> (8 * b)) & 0xffu) != 0u))
                                << (q * 16 + k * 4 + b);
            }
        } else {                                   // bf16
            const uint4* p = (const uint4*)mraw + (ebase >> 3);
#pragma unroll
            for (int q = 0; q < 4; q++) {
                uint4 v = p[q];
                uint32_t ws[4] = {v.x, v.y, v.z, v.w};
#pragma unroll
                for (int k = 0; k < 4; k++) {
                    bits |= ((uint32_t)((ws[k] & 0x7fffu) != 0u))         << (q * 8 + k * 2 + 0);
                    bits |= ((uint32_t)(((ws[k] >> 16) & 0x7fffu) != 0u)) << (q * 8 + k * 2 + 1);
                }
            }
        }
        dst[w] = bits;
    }
}

// ------------------------- fused HMMA tile kernel (R7 + 5-stage) ------------
extern __shared__ __align__(16) unsigned char dynsm[];

__global__ void __launch_bounds__(256, 2)
tile_kernel(const void* __restrict__ mraw) {
    // linear tile index -> (bi, bj), bi >= bj
    int t = blockIdx.x;
    int bi = (int)((sqrt(8.0 * t + 1.0) - 1.0) * 0.5);
    while ((bi + 1) * (bi + 2) / 2 <= t) bi++;
    while (bi * (bi + 1) / 2 > t) bi--;
    int bj = t - bi * (bi + 1) / 2;
    const bool diag    = (bi == bj);
    const bool ap_tile = (bi == bj + 32);

    const int tid  = threadIdx.x;
    const int wid  = tid >> 5;
    const int lane = tid & 31;
    const int wr   = wid & 3;     // warp row: 4 x 32 rows
    const int wc   = wid >> 2;    // warp col: 2 x 64 cols

    const uint32_t smb = smem_u32(dynsm);
    float*    sy2a  = (float*)(dynsm + OFF_SY2A);
    float*    sy2b  = (float*)(dynsm + OFF_SY2B);
    uint32_t* mrow  = (uint32_t*)(dynsm + OFF_MROW);
    uint32_t* mcol  = (uint32_t*)(dynsm + OFF_MCOL);
    float (*rowred)[2] = (float (*)[2])(dynsm + OFF_ROWRED);
    float (*colred)[4] = (float (*)[4])(dynsm + OFF_COLRED);

    if (tid < BM) sy2a[tid] = g_sqnorm[bi * BM + tid];
    else          sy2b[tid - BM] = g_sqnorm[bj * BM + (tid - BM)];

    // global-load mapping: 512 x 16B per 128x32 tile, 2 per thread
    const int lrow0 = tid >> 2;          // rows 0..63
    const int lrow1 = lrow0 + 64;        // rows 64..127
    const int q0    = tid & 3;           // 16B quad within 64B row-chunk

    const __half* pa_base = g_eh + (size_t)bi * BM * DDIM;
    const __half* pb_base = g_eh + (size_t)bj * BM * DDIM;
    const uint32_t sA0 = (uint32_t)(lrow0 * ROWB + q0 * 16);
    const uint32_t sA1 = (uint32_t)(lrow1 * ROWB + q0 * 16);

    // prologue: issue cp.async for chunks 0..3 into stages 0..3
#pragma unroll
    for (int s = 0; s < NSTAGE - 1; s++) {
        int k0 = s * 32;
        uint32_t ab = smb + s * 2 * STAGEB;
        uint32_t bb = ab + STAGEB;
        cpa16(ab + sA0, pa_base + (size_t)lrow0 * DDIM + k0 + q0 * 8);
        cpa16(ab + sA1, pa_base + (size_t)lrow1 * DDIM + k0 + q0 * 8);
        cpa16(bb + sA0, pb_base + (size_t)lrow0 * DDIM + k0 + q0 * 8);
        cpa16(bb + sA1, pb_base + (size_t)lrow1 * DDIM + k0 + q0 * 8);
        cpa_commit();
    }

    // per-tile mask packing into smem (LDG latency overlaps cp.async drain)
    {
        int mode = g_mask_mode;
        pack_rect(mraw, mode, bi * BM, bj * BM, mrow, tid);
        if (!diag) pack_rect(mraw, mode, bj * BM, bi * BM, mcol, tid);
    }

    // ldmatrix per-lane byte offsets
    const uint32_t aoff = (uint32_t)((wr * 32 + (lane & 15)) * ROWB + (lane >> 4) * 16);
    const uint32_t boff = (uint32_t)((wc * 64 + ((lane >> 4) & 1) * 8 + (lane & 7)) * ROWB
                                     + ((lane >> 3) & 1) * 16);

    float acc[2][8][4];
#pragma unroll
    for (int i = 0; i < 2; i++)
#pragma unroll
        for (int j = 0; j < 8; j++)
#pragma unroll
            for (int r = 0; r < 4; r++) acc[i][j][r] = 0.f;

#pragma unroll
    for (int c = 0; c < NCHUNK; c++) {
        cpa_wait<NSTAGE - 2>();   // chunk c arrived (3 groups may remain in flight)
        __syncthreads();          // + all threads done computing the stage to refill

        if (c + NSTAGE - 1 < NCHUNK) {
            const int k0 = (c + NSTAGE - 1) * 32;
            const int s  = (c + NSTAGE - 1) % NSTAGE;   // compile-time (full unroll)
            uint32_t ab = smb + s * 2 * STAGEB;
            uint32_t bb = ab + STAGEB;
            cpa16(ab + sA0, pa_base + (size_t)lrow0 * DDIM + k0 + q0 * 8);
            cpa16(ab + sA1, pa_base + (size_t)lrow1 * DDIM + k0 + q0 * 8);
            cpa16(bb + sA0, pb_base + (size_t)lrow0 * DDIM + k0 + q0 * 8);
            cpa16(bb + sA1, pb_base + (size_t)lrow1 * DDIM + k0 + q0 * 8);
        }
        cpa_commit();

        const uint32_t aB = smb + (c % NSTAGE) * 2 * STAGEB + aoff;
        const uint32_t bB = aB - aoff + STAGEB + boff;
#pragma unroll
        for (int ks = 0; ks < 2; ks++) {
            uint32_t afr[2][4];
            ldmx4(afr[0], aB + ks * 32);
            ldmx4(afr[1], aB + 16 * ROWB + ks * 32);
            uint32_t bfr[8][2];
#pragma unroll
            for (int fp = 0; fp < 4; fp++) {
                uint32_t r4[4];
                ldmx4(r4, bB + fp * 16 * ROWB + ks * 32);
                bfr[fp * 2 + 0][0] = r4[0]; bfr[fp * 2 + 0][1] = r4[1];
                bfr[fp * 2 + 1][0] = r4[2]; bfr[fp * 2 + 1][1] = r4[3];
            }
#pragma unroll
            for (int fm = 0; fm < 2; fm++)
#pragma unroll
                for (int fn = 0; fn < 8; fn++)
                    mma16816(acc[fm][fn], afr[fm], bfr[fn]);
        }
    }
    __syncthreads();   // mask pack + all MMA consumption done

    // ------------------------------ epilogue -------------------------------
    const int lq = lane >> 2;       // 0..7
    const int lr = lane & 3;        // 0..3
    const uint32_t* colm = diag ? mrow : mcol;

    float x2v[4];
#pragma unroll
    for (int fm = 0; fm < 2; fm++)
#pragma unroll
        for (int hm = 0; hm < 2; hm++)
            x2v[fm * 2 + hm] = sy2a[wr * 32 + fm * 16 + lq + hm * 8];

    float y2v[16];
#pragma unroll
    for (int fn = 0; fn < 8; fn++)
#pragma unroll
        for (int h = 0; h < 2; h++)
            y2v[fn * 2 + h] = sy2b[wc * 64 + fn * 8 + 2 * lr + h];

    uint32_t rw[8];
#pragma unroll
    for (int fm = 0; fm < 2; fm++)
#pragma unroll
        for (int hm = 0; hm < 2; hm++) {
            int mloc = wr * 32 + fm * 16 + lq + hm * 8;
#pragma unroll
            for (int k = 0; k < 2; k++)
                rw[(fm * 2 + hm) * 2 + k] = mrow[mloc * 4 + wc * 2 + k];
        }

    uint32_t cw[16];
#pragma unroll
    for (int fn = 0; fn < 8; fn++)
#pragma unroll
        for (int h = 0; h < 2; h++) {
            int nloc = wc * 64 + fn * 8 + 2 * lr + h;
            cw[fn * 2 + h] = colm[nloc * 4 + wr];
        }

    float rowp[4] = {0.f, 0.f, 0.f, 0.f};
    float colp[16];
#pragma unroll
    for (int i = 0; i < 16; i++) colp[i] = 0.f;

#pragma unroll
    for (int fm = 0; fm < 2; fm++)
#pragma unroll
        for (int fn = 0; fn < 8; fn++)
#pragma unroll
            for (int r = 0; r < 4; r++) {
                int hm = r >> 1, h = r & 1;
                int mloc = wr * 32 + fm * 16 + lq + hm * 8;
                int nloc = wc * 64 + fn * 8 + 2 * lr + h;
                float sq = x2v[fm * 2 + hm] + y2v[fn * 2 + h] - 2.f * acc[fm][fn][r];
                float dd = sqrtf(fmaxf(sq, 0.f) + 1e-12f);
                if (diag && mloc == nloc) dd = 1e-6f;   // exact self-distance
                if (ap_tile && mloc == nloc) g_ap[bj * BM + mloc] = dd;
                float ev = __expf(MARGIN - dd);
                int nn = fn * 8 + 2 * lr + h;           // 0..63 within wc half
                if ((rw[(fm * 2 + hm) * 2 + (nn >> 5)] >> (nn & 31)) & 1u)
                    rowp[fm * 2 + hm] += ev;
                if ((cw[fn * 2 + h] >> (fm * 16 + lq + hm * 8)) & 1u)
                    colp[fn * 2 + h] += ev;
            }

    // row partials: reduce over the 4-lane quad
#pragma unroll
    for (int i = 0; i < 4; i++) {
        rowp[i] += __shfl_xor_sync(0xffffffffu, rowp[i], 1);
        rowp[i] += __shfl_xor_sync(0xffffffffu, rowp[i], 2);
    }
    if (lr == 0) {
#pragma unroll
        for (int fm = 0; fm < 2; fm++)
#pragma unroll
            for (int hm = 0; hm < 2; hm++)
                rowred[wr * 32 + fm * 16 + lq + hm * 8][wc] = rowp[fm * 2 + hm];
    }

    // col partials: reduce over lq (xor 4, 8, 16)
#pragma unroll
    for (int i = 0; i < 16; i++) {
        colp[i] += __shfl_xor_sync(0xffffffffu, colp[i], 4);
        colp[i] += __shfl_xor_sync(0xffffffffu, colp[i], 8);
        colp[i] += __shfl_xor_sync(0xffffffffu, colp[i], 16);
    }
    if (lane < 4) {
#pragma unroll
        for (int fn = 0; fn < 8; fn++)
#pragma unroll
            for (int h = 0; h < 2; h++)
                colred[wc * 64 + fn * 8 + 2 * lane + h][wr] = colp[fn * 2 + h];
    }
    __syncthreads();

    if (tid < BM) {
        g_partial[(size_t)bj * TWO_N + bi * BM + tid] = rowred[tid][0] + rowred[tid][1];
        if (!diag)
            g_partial[(size_t)bi * TWO_N + bj * BM + tid] =
                colred[tid][0] + colred[tid][1] + colred[tid][2] + colred[tid][3];
    }
}

// ------------------------- fused loss reduction -----------------------------
__global__ void loss_stage1() {
    __shared__ float ssum[256];
    __shared__ int   scnt[256];
    int tid = threadIdx.x;
    int i   = blockIdx.x * 256 + tid;          // anchor index 0..4095

    float rs = 0.f;
#pragma unroll
    for (int c = 0; c < NBJ; c++) rs += g_partial[(size_t)c * TWO_N + i];
    float rs2 = 0.f;
#pragma unroll
    for (int c = 0; c < NBJ; c++) rs2 += g_partial[(size_t)c * TWO_N + i + NHALF];
    rs += rs2;

    float j = logf(rs) + g_ap[i];
    float s = 0.f;
    int   cnt = 0;
    if (!isnan(j)) {
        cnt = 1;
        float tt = fmaxf(j, 0.f);
        s = tt * tt;
    }
    ssum[tid] = s;
    scnt[tid] = cnt;
    __syncthreads();
    for (int o = 128; o > 0; o >>= 1) {
        if (tid < o) { ssum[tid] += ssum[tid + o]; scnt[tid] += scnt[tid + o]; }
        __syncthreads();
    }
    if (tid == 0) { g_bsum[blockIdx.x] = ssum[0]; g_bcnt[blockIdx.x] = scnt[0]; }
}

__global__ void loss_stage2(float* __restrict__ out) {
    int tid = threadIdx.x;           // 32 threads
    float s = (tid < NBLK1) ? g_bsum[tid] : 0.f;
    int   c = (tid < NBLK1) ? g_bcnt[tid] : 0;
#pragma unroll
    for (int o = 16; o > 0; o >>= 1) {
        s += __shfl_xor_sync(0xffffffffu, s, o);
        c += __shfl_xor_sync(0xffffffffu, c, o);
    }
    if (tid == 0) {
        float cnt = fmaxf((float)c, 1.f);
        out[0] = s / cnt * 0.5f;
    }
}

// ---------------------------------------------------------------------------
extern "C" void kernel_launch(void* const* d_in, const int* in_sizes, int n_in,
                              void* d_out, int out_size) {
    const float* E    = (const float*)d_in[0];
    const void*  mask = d_in[1];
    float*       out  = (float*)d_out;

    prep_kernel<<<(TWO_N * 32) / 512, 512>>>(E, (const unsigned int*)mask);

    cudaFuncSetAttribute(tile_kernel, cudaFuncAttributeMaxDynamicSharedMemorySize,
                         SMEM_TOTAL);
    tile_kernel<<<NTILE, 256, SMEM_TOTAL>>>(mask);

    loss_stage1<<<NBLK1, 256>>>();
    loss_stage2<<<1, 32>>>(out);
}

// round 15
// speedup vs baseline: 1.0693x; 1.0693x over previous
#include <cuda_runtime.h>
#include <cuda_fp16.h>
#include <math.h>
#include <stdint.h>

#define TWO_N 8192
#define DDIM  256
#define NHALF 4096
#define BM    128
#define NBJ   64
#define NTILE (NBJ * (NBJ + 1) / 2)   /* 2080 lower-triangle pairs */
#define MARGIN 0.5f
#define NCHUNK 8                       /* 8 chunks of K=32 */
#define NSTAGE 4
#define ROWB   80                      /* smem row stride bytes (32 halfs + 8 pad) */
#define STAGEB (BM * ROWB)             /* 10240 B per (A or B) stage */
#define NBLK1  16                      /* stage-1 reduction blocks */

/* dynamic smem layout (bytes) */
#define OFF_MROW    (NSTAGE * 2 * STAGEB)          /* 81920: row-rect mask 2KB */
#define OFF_MCOL    (OFF_MROW + 2048)              /* col-rect mask 2KB */
#define OFF_SY2A    (OFF_MCOL + 2048)
#define OFF_SY2B    (OFF_SY2A + 512)
#define OFF_ROWRED  (OFF_SY2B + 512)               /* 128*2 floats */
#define OFF_COLRED  (OFF_ROWRED + 1024)            /* 128*4 floats */
#define SMEM_TOTAL  (OFF_COLRED + 2048)            /* 90112 B */

// ------------------------- device scratch (no allocs allowed) --------------
__device__ float    g_sqnorm[TWO_N];
__device__ float    g_partial[NBJ * TWO_N];
__device__ float    g_ap[NHALF];
__device__ int      g_mask_mode;   // 0=int32 1=uint8 2=float32 3=bf16
__device__ __half   g_eh[TWO_N * DDIM];                 // 4 MB fp16 embeddings
__device__ float    g_bsum[NBLK1];
__device__ int      g_bcnt[NBLK1];

// ------------------------- helpers -----------------------------------------
__device__ __forceinline__ uint32_t smem_u32(const void* p) {
    uint32_t a;
    asm("{ .reg .u64 t; cvta.to.shared.u64 t, %1; cvt.u32.u64 %0, t; }"
        : "=r"(a) : "l"(p));
    return a;
}
__device__ __forceinline__ void cpa16(uint32_t dst, const void* src) {
    asm volatile("cp.async.cg.shared.global [%0], [%1], 16;" :: "r"(dst), "l"(src));
}
__device__ __forceinline__ void cpa_commit() {
    asm volatile("cp.async.commit_group;" ::: "memory");
}
template <int N>
__device__ __forceinline__ void cpa_wait() {
    asm volatile("cp.async.wait_group %0;" :: "n"(N) : "memory");
}
__device__ __forceinline__ void ldmx4(uint32_t* r, uint32_t addr) {
    asm volatile("ldmatrix.sync.aligned.m8n8.x4.shared.b16 {%0,%1,%2,%3}, [%4];"
                 : "=r"(r[0]), "=r"(r[1]), "=r"(r[2]), "=r"(r[3]) : "r"(addr));
}
__device__ __forceinline__ void mma16816(float* c, const uint32_t* a, const uint32_t* b) {
    asm volatile(
        "mma.sync.aligned.m16n8k16.row.col.f32.f16.f16.f32 "
        "{%0,%1,%2,%3}, {%4,%5,%6,%7}, {%8,%9}, {%0,%1,%2,%3};"
        : "+f"(c[0]), "+f"(c[1]), "+f"(c[2]), "+f"(c[3])
        : "r"(a[0]), "r"(a[1]), "r"(a[2]), "r"(a[3]), "r"(b[0]), "r"(b[1]));
}
// fast distance: d = s * rsqrt.approx(s)  (s >= 1e-12 keeps it finite)
__device__ __forceinline__ float fast_dist(float s) {
    float r;
    asm("rsqrt.approx.f32 %0, %1;" : "=f"(r) : "f"(s));
    return s * r;
}

// ------------------------- prep: detect + sqnorm + fp16 convert -------------
__global__ void prep_kernel(const float* __restrict__ E,
                            const unsigned int* __restrict__ mraw) {
    if (blockIdx.x == 0) {
        __shared__ int has_gt1, has_f32one, has_bf16pat;
        if (threadIdx.x == 0) { has_gt1 = 0; has_f32one = 0; has_bf16pat = 0; }
        __syncthreads();
        for (int i = threadIdx.x; i < 1024; i += blockDim.x) {
            unsigned int w = mraw[i];
            if (w == 0x3F803F80u || w == 0x00003F80u) atomicOr(&has_bf16pat, 1);
            else if (w == 0x3F800000u)                atomicOr(&has_f32one, 1);
            else if (w > 1u)                          atomicOr(&has_gt1, 1);
        }
        __syncthreads();
        if (threadIdx.x == 0) {
            int mode;
            if (has_bf16pat)      mode = 3;
            else if (has_f32one)  mode = 2;
            else if (has_gt1)     mode = 1;
            else                  mode = 0;
            g_mask_mode = mode;
        }
    }

    int warp = (blockIdx.x * blockDim.x + threadIdx.x) >> 5;
    int lane = threadIdx.x & 31;
    if (warp >= TWO_N) return;
    const float* row = E + (size_t)warp * DDIM;
    float4 v0 = ((const float4*)row)[lane * 2];
    float4 v1 = ((const float4*)row)[lane * 2 + 1];
    float s = v0.x * v0.x;
    s = fmaf(v0.y, v0.y, s); s = fmaf(v0.z, v0.z, s); s = fmaf(v0.w, v0.w, s);
    s = fmaf(v1.x, v1.x, s); s = fmaf(v1.y, v1.y, s);
    s = fmaf(v1.z, v1.z, s); s = fmaf(v1.w, v1.w, s);
    __half2 h[4];
    h[0] = __floats2half2_rn(v0.x, v0.y);
    h[1] = __floats2half2_rn(v0.z, v0.w);
    h[2] = __floats2half2_rn(v1.x, v1.y);
    h[3] = __floats2half2_rn(v1.z, v1.w);
    *(uint4*)(g_eh + (size_t)warp * DDIM + lane * 8) = *(uint4*)h;
#pragma unroll
    for (int o = 16; o > 0; o >>= 1) s += __shfl_xor_sync(0xffffffffu, s, o);
    if (lane == 0) g_sqnorm[warp] = s;
}

// ------------------------- per-tile mask packing into smem ------------------
__device__ __forceinline__ void pack_rect(const void* __restrict__ mraw, int mode,
                                          int rowbase, int colbase,
                                          uint32_t* __restrict__ dst, int tid) {
#pragma unroll
    for (int w = tid; w < 512; w += 256) {
        int rr = w >> 2, wq = w & 3;
        size_t ebase = (size_t)(rowbase + rr) * TWO_N + colbase + wq * 32;
        uint32_t bits = 0u;
        if (mode == 0 || mode == 2) {              // int32 / float32 (4 B/elem)
            const uint4* p = (const uint4*)mraw + (ebase >> 2);
            uint32_t vm = (mode == 2) ? 0x7fffffffu : 0xffffffffu;
#pragma unroll
            for (int q = 0; q < 8; q++) {
                uint4 v = p[q];
                bits |= ((uint32_t)((v.x & vm) != 0u)) << (q * 4 + 0);
                bits |= ((uint32_t)((v.y & vm) != 0u)) << (q * 4 + 1);
                bits |= ((uint32_t)((v.z & vm) != 0u)) << (q * 4 + 2);
                bits |= ((uint32_t)((v.w & vm) != 0u)) << (q * 4 + 3);
            }
        } else if (mode == 1) {                    // uint8
            const uint4* p = (const uint4*)mraw + (ebase >> 4);
#pragma unroll
            for (int q = 0; q < 2; q++) {
                uint4 v = p[q];
                uint32_t ws[4] = {v.x, v.y, v.z, v.w};
#pragma unroll
                for (int k = 0; k < 4; k++)
#pragma unroll
                    for (int b = 0; b < 4; b++)
                        bits |= ((uint32_t)(((ws[k] >> (8 * b)) & 0xffu) != 0u))
                                << (q * 16 + k * 4 + b);
            }
        } else {                                   // bf16
            const uint4* p = (const uint4*)mraw + (ebase >> 3);
#pragma unroll
            for (int q = 0; q < 4; q++) {
                uint4 v = p[q];
                uint32_t ws[4] = {v.x, v.y, v.z, v.w};
#pragma unroll
                for (int k = 0; k < 4; k++) {
                    bits |= ((uint32_t)((ws[k] & 0x7fffu) != 0u))         << (q * 8 + k * 2 + 0);
                    bits |= ((uint32_t)(((ws[k] >> 16) & 0x7fffu) != 0u)) << (q * 8 + k * 2 + 1);
                }
            }
        }
        dst[w] = bits;
    }
}

// ------------------------- fused HMMA tile kernel (R13 structure) -----------
extern __shared__ __align__(16) unsigned char dynsm[];

__global__ void __launch_bounds__(256, 2)
tile_kernel(const void* __restrict__ mraw) {
    // linear tile index -> (bi, bj), bi >= bj
    int t = blockIdx.x;
    int bi = (int)((sqrt(8.0 * t + 1.0) - 1.0) * 0.5);
    while ((bi + 1) * (bi + 2) / 2 <= t) bi++;
    while (bi * (bi + 1) / 2 > t) bi--;
    int bj = t - bi * (bi + 1) / 2;
    const bool diag    = (bi == bj);
    const bool ap_tile = (bi == bj + 32);

    const int tid  = threadIdx.x;
    const int wid  = tid >> 5;
    const int lane = tid & 31;
    const int wr   = wid & 3;     // warp row: 4 x 32 rows
    const int wc   = wid >> 2;    // warp col: 2 x 64 cols

    const uint32_t smb = smem_u32(dynsm);
    float*    sy2a  = (float*)(dynsm + OFF_SY2A);
    float*    sy2b  = (float*)(dynsm + OFF_SY2B);
    uint32_t* mrow  = (uint32_t*)(dynsm + OFF_MROW);
    uint32_t* mcol  = (uint32_t*)(dynsm + OFF_MCOL);
    float (*rowred)[2] = (float (*)[2])(dynsm + OFF_ROWRED);
    float (*colred)[4] = (float (*)[4])(dynsm + OFF_COLRED);

    if (tid < BM) sy2a[tid] = g_sqnorm[bi * BM + tid];
    else          sy2b[tid - BM] = g_sqnorm[bj * BM + (tid - BM)];

    // global-load mapping: 512 x 16B per 128x32 tile, 2 per thread
    const int lrow0 = tid >> 2;          // rows 0..63
    const int lrow1 = lrow0 + 64;        // rows 64..127
    const int q0    = tid & 3;           // 16B quad within 64B row-chunk

    const __half* pa_base = g_eh + (size_t)bi * BM * DDIM;
    const __half* pb_base = g_eh + (size_t)bj * BM * DDIM;
    const uint32_t sA0 = (uint32_t)(lrow0 * ROWB + q0 * 16);
    const uint32_t sA1 = (uint32_t)(lrow1 * ROWB + q0 * 16);

    // prologue: issue cp.async for chunks 0..2
#pragma unroll
    for (int s = 0; s < NSTAGE - 1; s++) {
        int k0 = s * 32;
        uint32_t ab = smb + s * 2 * STAGEB;
        uint32_t bb = ab + STAGEB;
        cpa16(ab + sA0, pa_base + (size_t)lrow0 * DDIM + k0 + q0 * 8);
        cpa16(ab + sA1, pa_base + (size_t)lrow1 * DDIM + k0 + q0 * 8);
        cpa16(bb + sA0, pb_base + (size_t)lrow0 * DDIM + k0 + q0 * 8);
        cpa16(bb + sA1, pb_base + (size_t)lrow1 * DDIM + k0 + q0 * 8);
        cpa_commit();
    }

    // per-tile mask packing into smem (LDG latency overlaps cp.async drain)
    {
        int mode = g_mask_mode;
        pack_rect(mraw, mode, bi * BM, bj * BM, mrow, tid);
        if (!diag) pack_rect(mraw, mode, bj * BM, bi * BM, mcol, tid);
    }

    // ldmatrix per-lane byte offsets
    const uint32_t aoff = (uint32_t)((wr * 32 + (lane & 15)) * ROWB + (lane >> 4) * 16);
    const uint32_t boff = (uint32_t)((wc * 64 + ((lane >> 4) & 1) * 8 + (lane & 7)) * ROWB
                                     + ((lane >> 3) & 1) * 16);

    float acc[2][8][4];
#pragma unroll
    for (int i = 0; i < 2; i++)
#pragma unroll
        for (int j = 0; j < 8; j++)
#pragma unroll
            for (int r = 0; r < 4; r++) acc[i][j][r] = 0.f;

    for (int c = 0; c < NCHUNK; c++) {
        cpa_wait<NSTAGE - 2>();   // stage c arrived
        __syncthreads();          // + all threads done computing stage c-1

        if (c + NSTAGE - 1 < NCHUNK) {
            int k0 = (c + NSTAGE - 1) * 32;
            int s  = (c + NSTAGE - 1) & (NSTAGE - 1);
            uint32_t ab = smb + s * 2 * STAGEB;
            uint32_t bb = ab + STAGEB;
            cpa16(ab + sA0, pa_base + (size_t)lrow0 * DDIM + k0 + q0 * 8);
            cpa16(ab + sA1, pa_base + (size_t)lrow1 * DDIM + k0 + q0 * 8);
            cpa16(bb + sA0, pb_base + (size_t)lrow0 * DDIM + k0 + q0 * 8);
            cpa16(bb + sA1, pb_base + (size_t)lrow1 * DDIM + k0 + q0 * 8);
        }
        cpa_commit();

        const uint32_t aB = smb + (c & (NSTAGE - 1)) * 2 * STAGEB + aoff;
        const uint32_t bB = aB - aoff + STAGEB + boff;
#pragma unroll
        for (int ks = 0; ks < 2; ks++) {
            uint32_t afr[2][4];
            ldmx4(afr[0], aB + ks * 32);
            ldmx4(afr[1], aB + 16 * ROWB + ks * 32);
            uint32_t bfr[8][2];
#pragma unroll
            for (int fp = 0; fp < 4; fp++) {
                uint32_t r4[4];
                ldmx4(r4, bB + fp * 16 * ROWB + ks * 32);
                bfr[fp * 2 + 0][0] = r4[0]; bfr[fp * 2 + 0][1] = r4[1];
                bfr[fp * 2 + 1][0] = r4[2]; bfr[fp * 2 + 1][1] = r4[3];
            }
#pragma unroll
            for (int fm = 0; fm < 2; fm++)
#pragma unroll
                for (int fn = 0; fn < 8; fn++)
                    mma16816(acc[fm][fn], afr[fm], bfr[fn]);
        }
    }
    __syncthreads();   // mask pack + all MMA consumption done

    // ------------------------------ epilogue -------------------------------
    const int lq = lane >> 2;       // 0..7
    const int lr = lane & 3;        // 0..3
    const uint32_t* colm = diag ? mrow : mcol;

    float x2v[4];
#pragma unroll
    for (int fm = 0; fm < 2; fm++)
#pragma unroll
        for (int hm = 0; hm < 2; hm++)
            x2v[fm * 2 + hm] = sy2a[wr * 32 + fm * 16 + lq + hm * 8];

    float y2v[16];
#pragma unroll
    for (int fn = 0; fn < 8; fn++)
#pragma unroll
        for (int h = 0; h < 2; h++)
            y2v[fn * 2 + h] = sy2b[wc * 64 + fn * 8 + 2 * lr + h];

    uint32_t rw[8];
#pragma unroll
    for (int fm = 0; fm < 2; fm++)
#pragma unroll
        for (int hm = 0; hm < 2; hm++) {
            int mloc = wr * 32 + fm * 16 + lq + hm * 8;
#pragma unroll
            for (int k = 0; k < 2; k++)
                rw[(fm * 2 + hm) * 2 + k] = mrow[mloc * 4 + wc * 2 + k];
        }

    uint32_t cw[16];
#pragma unroll
    for (int fn = 0; fn < 8; fn++)
#pragma unroll
        for (int h = 0; h < 2; h++) {
            int nloc = wc * 64 + fn * 8 + 2 * lr + h;
            cw[fn * 2 + h] = colm[nloc * 4 + wr];
        }

    float rowp[4] = {0.f, 0.f, 0.f, 0.f};
    float colp[16];
#pragma unroll
    for (int i = 0; i < 16; i++) colp[i] = 0.f;

#pragma unroll
    for (int fm = 0; fm < 2; fm++)
#pragma unroll
        for (int fn = 0; fn < 8; fn++)
#pragma unroll
            for (int r = 0; r < 4; r++) {
                int hm = r >> 1, h = r & 1;
                int mloc = wr * 32 + fm * 16 + lq + hm * 8;
                int nloc = wc * 64 + fn * 8 + 2 * lr + h;
                float sq = x2v[fm * 2 + hm] + y2v[fn * 2 + h] - 2.f * acc[fm][fn][r];
                float dd = fast_dist(fmaxf(sq, 0.f) + 1e-12f);
                if (diag && mloc == nloc) dd = 1e-6f;   // exact self-distance
                if (ap_tile && mloc == nloc) g_ap[bj * BM + mloc] = dd;
                float ev = __expf(MARGIN - dd);
                int nn = fn * 8 + 2 * lr + h;           // 0..63 within wc half
                if ((rw[(fm * 2 + hm) * 2 + (nn >> 5)] >> (nn & 31)) & 1u)
                    rowp[fm * 2 + hm] += ev;
                if ((cw[fn * 2 + h] >> (fm * 16 + lq + hm * 8)) & 1u)
                    colp[fn * 2 + h] += ev;
            }

    // row partials: reduce over the 4-lane quad
#pragma unroll
    for (int i = 0; i < 4; i++) {
        rowp[i] += __shfl_xor_sync(0xffffffffu, rowp[i], 1);
        rowp[i] += __shfl_xor_sync(0xffffffffu, rowp[i], 2);
    }
    if (lr == 0) {
#pragma unroll
        for (int fm = 0; fm < 2; fm++)
#pragma unroll
            for (int hm = 0; hm < 2; hm++)
                rowred[wr * 32 + fm * 16 + lq + hm * 8][wc] = rowp[fm * 2 + hm];
    }

    // col partials: reduce over lq (xor 4, 8, 16)
#pragma unroll
    for (int i = 0; i < 16; i++) {
        colp[i] += __shfl_xor_sync(0xffffffffu, colp[i], 4);
        colp[i] += __shfl_xor_sync(0xffffffffu, colp[i], 8);
        colp[i] += __shfl_xor_sync(0xffffffffu, colp[i], 16);
    }
    if (lane < 4) {
#pragma unroll
        for (int fn = 0; fn < 8; fn++)
#pragma unroll
            for (int h = 0; h < 2; h++)
                colred[wc * 64 + fn * 8 + 2 * lane + h][wr] = colp[fn * 2 + h];
    }
    __syncthreads();

    if (tid < BM) {
        g_partial[(size_t)bj * TWO_N + bi * BM + tid] = rowred[tid][0] + rowred[tid][1];
        if (!diag)
            g_partial[(size_t)bi * TWO_N + bj * BM + tid] =
                colred[tid][0] + colred[tid][1] + colred[tid][2] + colred[tid][3];
    }
}

// ------------------------- fused loss reduction -----------------------------
__global__ void loss_stage1() {
    __shared__ float ssum[256];
    __shared__ int   scnt[256];
    int tid = threadIdx.x;
    int i   = blockIdx.x * 256 + tid;          // anchor index 0..4095

    float rs = 0.f;
#pragma unroll
    for (int c = 0; c < NBJ; c++) rs += g_partial[(size_t)c * TWO_N + i];
    float rs2 = 0.f;
#pragma unroll
    for (int c = 0; c < NBJ; c++) rs2 += g_partial[(size_t)c * TWO_N + i + NHALF];
    rs += rs2;

    float j = logf(rs) + g_ap[i];
    float s = 0.f;
    int   cnt = 0;
    if (!isnan(j)) {
        cnt = 1;
        float tt = fmaxf(j, 0.f);
        s = tt * tt;
    }
    ssum[tid] = s;
    scnt[tid] = cnt;
    __syncthreads();
    for (int o = 128; o > 0; o >>= 1) {
        if (tid < o) { ssum[tid] += ssum[tid + o]; scnt[tid] += scnt[tid + o]; }
        __syncthreads();
    }
    if (tid == 0) { g_bsum[blockIdx.x] = ssum[0]; g_bcnt[blockIdx.x] = scnt[0]; }
}

__global__ void loss_stage2(float* __restrict__ out) {
    int tid = threadIdx.x;           // 32 threads
    float s = (tid < NBLK1) ? g_bsum[tid] : 0.f;
    int   c = (tid < NBLK1) ? g_bcnt[tid] : 0;
#pragma unroll
    for (int o = 16; o > 0; o >>= 1) {
        s += __shfl_xor_sync(0xffffffffu, s, o);
        c += __shfl_xor_sync(0xffffffffu, c, o);
    }
    if (tid == 0) {
        float cnt = fmaxf((float)c, 1.f);
        out[0] = s / cnt * 0.5f;
    }
}

// ---------------------------------------------------------------------------
extern "C" void kernel_launch(void* const* d_in, const int* in_sizes, int n_in,
                              void* d_out, int out_size) {
    const float* E    = (const float*)d_in[0];
    const void*  mask = d_in[1];
    float*       out  = (float*)d_out;

    prep_kernel<<<(TWO_N * 32) / 256, 256>>>(E, (const unsigned int*)mask);

    cudaFuncSetAttribute(tile_kernel, cudaFuncAttributeMaxDynamicSharedMemorySize,
                         SMEM_TOTAL);
    tile_kernel<<<NTILE, 256, SMEM_TOTAL>>>(mask);

    loss_stage1<<<NBLK1, 256>>>();
    loss_stage2<<<1, 32>>>(out);
}

// round 16
// speedup vs baseline: 1.0888x; 1.0182x over previous
#include <cuda_runtime.h>
#include <cuda_fp16.h>
#include <math.h>
#include <stdint.h>

#define TWO_N 8192
#define DDIM  256
#define NHALF 4096
#define BM    128
#define NBJ   64
#define NTILE (NBJ * (NBJ + 1) / 2)   /* 2080 lower-triangle pairs */
#define MARGIN 0.5f
#define NCHUNK 8                       /* 8 chunks of K=32 */
#define NSTAGE 4
#define ROWB   80                      /* smem row stride bytes (32 halfs + 8 pad) */
#define STAGEB (BM * ROWB)             /* 10240 B per (A or B) stage */
#define NBLK1  32                      /* stage-1 reduction blocks */
#define L2E    1.4426950408889634f

/* dynamic smem layout (bytes) */
#define OFF_MROW    (NSTAGE * 2 * STAGEB)          /* 81920: row-rect mask 2KB */
#define OFF_MCOL    (OFF_MROW + 2048)              /* col-rect mask 2KB */
#define OFF_SY2A    (OFF_MCOL + 2048)
#define OFF_SY2B    (OFF_SY2A + 512)
#define OFF_ROWRED  (OFF_SY2B + 512)               /* 128*2 floats */
#define OFF_COLRED  (OFF_ROWRED + 1024)            /* 128*4 floats */
#define SMEM_TOTAL  (OFF_COLRED + 2048)            /* 90112 B */

// ------------------------- device scratch (no allocs allowed) --------------
__device__ float    g_sqnorm[TWO_N];
__device__ float    g_partial[NBJ * TWO_N];
__device__ float    g_ap[NHALF];
__device__ int      g_mask_mode;   // 0=int32 1=uint8 2=float32 3=bf16
__device__ __half   g_eh[TWO_N * DDIM];                 // 4 MB fp16 embeddings
__device__ volatile float g_bsum[NBLK1];
__device__ volatile int   g_bcnt[NBLK1];
__device__ int      g_done;        // ticket counter (reset by folding block)

// ------------------------- helpers -----------------------------------------
__device__ __forceinline__ uint32_t smem_u32(const void* p) {
    uint32_t a;
    asm("{ .reg .u64 t; cvta.to.shared.u64 t, %1; cvt.u32.u64 %0, t; }"
        : "=r"(a) : "l"(p));
    return a;
}
__device__ __forceinline__ void cpa16(uint32_t dst, const void* src) {
    asm volatile("cp.async.cg.shared.global [%0], [%1], 16;" :: "r"(dst), "l"(src));
}
__device__ __forceinline__ void cpa_commit() {
    asm volatile("cp.async.commit_group;" ::: "memory");
}
template <int N>
__device__ __forceinline__ void cpa_wait() {
    asm volatile("cp.async.wait_group %0;" :: "n"(N) : "memory");
}
__device__ __forceinline__ void ldmx4(uint32_t* r, uint32_t addr) {
    asm volatile("ldmatrix.sync.aligned.m8n8.x4.shared.b16 {%0,%1,%2,%3}, [%4];"
                 : "=r"(r[0]), "=r"(r[1]), "=r"(r[2]), "=r"(r[3]) : "r"(addr));
}
__device__ __forceinline__ void mma16816(float* c, const uint32_t* a, const uint32_t* b) {
    asm volatile(
        "mma.sync.aligned.m16n8k16.row.col.f32.f16.f16.f32 "
        "{%0,%1,%2,%3}, {%4,%5,%6,%7}, {%8,%9}, {%0,%1,%2,%3};"
        : "+f"(c[0]), "+f"(c[1]), "+f"(c[2]), "+f"(c[3])
        : "r"(a[0]), "r"(a[1]), "r"(a[2]), "r"(a[3]), "r"(b[0]), "r"(b[1]));
}
// fast distance: d = s * rsqrt.approx(s)  (s >= 1e-12 keeps it finite)
__device__ __forceinline__ float fast_dist(float s) {
    float r;
    asm("rsqrt.approx.f32 %0, %1;" : "=f"(r) : "f"(s));
    return s * r;
}
// exp(MARGIN - d) = exp2(fma(-L2E, d, MARGIN*L2E))
__device__ __forceinline__ float fast_expm(float d) {
    float e;
    float x = fmaf(-L2E, d, MARGIN * L2E);
    asm("ex2.approx.f32 %0, %1;" : "=f"(e) : "f"(x));
    return e;
}

// ------------------------- prep: detect + sqnorm + fp16 convert -------------
__global__ void prep_kernel(const float* __restrict__ E,
                            const unsigned int* __restrict__ mraw) {
    if (blockIdx.x == 0) {
        __shared__ int has_gt1, has_f32one, has_bf16pat;
        if (threadIdx.x == 0) { has_gt1 = 0; has_f32one = 0; has_bf16pat = 0; }
        __syncthreads();
        for (int i = threadIdx.x; i < 1024; i += blockDim.x) {
            unsigned int w = mraw[i];
            if (w == 0x3F803F80u || w == 0x00003F80u) atomicOr(&has_bf16pat, 1);
            else if (w == 0x3F800000u)                atomicOr(&has_f32one, 1);
            else if (w > 1u)                          atomicOr(&has_gt1, 1);
        }
        __syncthreads();
        if (threadIdx.x == 0) {
            int mode;
            if (has_bf16pat)      mode = 3;
            else if (has_f32one)  mode = 2;
            else if (has_gt1)     mode = 1;
            else                  mode = 0;
            g_mask_mode = mode;
        }
    }

    int warp = (blockIdx.x * blockDim.x + threadIdx.x) >> 5;
    int lane = threadIdx.x & 31;
    if (warp >= TWO_N) return;
    const float* row = E + (size_t)warp * DDIM;
    float4 v0 = ((const float4*)row)[lane * 2];
    float4 v1 = ((const float4*)row)[lane * 2 + 1];
    float s = v0.x * v0.x;
    s = fmaf(v0.y, v0.y, s); s = fmaf(v0.z, v0.z, s); s = fmaf(v0.w, v0.w, s);
    s = fmaf(v1.x, v1.x, s); s = fmaf(v1.y, v1.y, s);
    s = fmaf(v1.z, v1.z, s); s = fmaf(v1.w, v1.w, s);
    __half2 h[4];
    h[0] = __floats2half2_rn(v0.x, v0.y);
    h[1] = __floats2half2_rn(v0.z, v0.w);
    h[2] = __floats2half2_rn(v1.x, v1.y);
    h[3] = __floats2half2_rn(v1.z, v1.w);
    *(uint4*)(g_eh + (size_t)warp * DDIM + lane * 8) = *(uint4*)h;
#pragma unroll
    for (int o = 16; o > 0; o >>= 1) s += __shfl_xor_sync(0xffffffffu, s, o);
    if (lane == 0) g_sqnorm[warp] = s;
}

// ------------------------- per-tile mask packing into smem ------------------
__device__ __forceinline__ void pack_rect(const void* __restrict__ mraw, int mode,
                                          int rowbase, int colbase,
                                          uint32_t* __restrict__ dst, int tid) {
#pragma unroll
    for (int w = tid; w < 512; w += 256) {
        int rr = w >> 2, wq = w & 3;
        size_t ebase = (size_t)(rowbase + rr) * TWO_N + colbase + wq * 32;
        uint32_t bits = 0u;
        if (mode == 0 || mode == 2) {              // int32 / float32 (4 B/elem)
            const uint4* p = (const uint4*)mraw + (ebase >> 2);
            uint32_t vm = (mode == 2) ? 0x7fffffffu : 0xffffffffu;
#pragma unroll
            for (int q = 0; q < 8; q++) {
                uint4 v = p[q];
                bits |= ((uint32_t)((v.x & vm) != 0u)) << (q * 4 + 0);
                bits |= ((uint32_t)((v.y & vm) != 0u)) << (q * 4 + 1);
                bits |= ((uint32_t)((v.z & vm) != 0u)) << (q * 4 + 2);
                bits |= ((uint32_t)((v.w & vm) != 0u)) << (q * 4 + 3);
            }
        } else if (mode == 1) {                    // uint8
            const uint4* p = (const uint4*)mraw + (ebase >> 4);
#pragma unroll
            for (int q = 0; q < 2; q++) {
                uint4 v = p[q];
                uint32_t ws[4] = {v.x, v.y, v.z, v.w};
#pragma unroll
                for (int k = 0; k < 4; k++)
#pragma unroll
                    for (int b = 0; b < 4; b++)
                        bits |= ((uint32_t)(((ws[k] >> (8 * b)) & 0xffu) != 0u))
                                << (q * 16 + k * 4 + b);
            }
        } else {                                   // bf16
            const uint4* p = (const uint4*)mraw + (ebase >> 3);
#pragma unroll
            for (int q = 0; q < 4; q++) {
                uint4 v = p[q];
                uint32_t ws[4] = {v.x, v.y, v.z, v.w};
#pragma unroll
                for (int k = 0; k < 4; k++) {
                    bits |= ((uint32_t)((ws[k] & 0x7fffu) != 0u))         << (q * 8 + k * 2 + 0);
                    bits |= ((uint32_t)(((ws[k] >> 16) & 0x7fffu) != 0u)) << (q * 8 + k * 2 + 1);
                }
            }
        }
        dst[w] = bits;
    }
}

// ------------------------- fused HMMA tile kernel (R13 structure) -----------
extern __shared__ __align__(16) unsigned char dynsm[];

__global__ void __launch_bounds__(256, 2)
tile_kernel(const void* __restrict__ mraw) {
    // linear tile index -> (bi, bj), bi >= bj
    int t = blockIdx.x;
    int bi = (int)((sqrt(8.0 * t + 1.0) - 1.0) * 0.5);
    while ((bi + 1) * (bi + 2) / 2 <= t) bi++;
    while (bi * (bi + 1) / 2 > t) bi--;
    int bj = t - bi * (bi + 1) / 2;
    const bool diag    = (bi == bj);
    const bool ap_tile = (bi == bj + 32);

    const int tid  = threadIdx.x;
    const int wid  = tid >> 5;
    const int lane = tid & 31;
    const int wr   = wid & 3;     // warp row: 4 x 32 rows
    const int wc   = wid >> 2;    // warp col: 2 x 64 cols

    const uint32_t smb = smem_u32(dynsm);
    float*    sy2a  = (float*)(dynsm + OFF_SY2A);
    float*    sy2b  = (float*)(dynsm + OFF_SY2B);
    uint32_t* mrow  = (uint32_t*)(dynsm + OFF_MROW);
    uint32_t* mcol  = (uint32_t*)(dynsm + OFF_MCOL);
    float (*rowred)[2] = (float (*)[2])(dynsm + OFF_ROWRED);
    float (*colred)[4] = (float (*)[4])(dynsm + OFF_COLRED);

    if (tid < BM) sy2a[tid] = g_sqnorm[bi * BM + tid];
    else          sy2b[tid - BM] = g_sqnorm[bj * BM + (tid - BM)];

    // global-load mapping: 512 x 16B per 128x32 tile, 2 per thread
    const int lrow0 = tid >> 2;          // rows 0..63
    const int lrow1 = lrow0 + 64;        // rows 64..127
    const int q0    = tid & 3;           // 16B quad within 64B row-chunk

    const __half* pa_base = g_eh + (size_t)bi * BM * DDIM;
    const __half* pb_base = g_eh + (size_t)bj * BM * DDIM;
    const uint32_t sA0 = (uint32_t)(lrow0 * ROWB + q0 * 16);
    const uint32_t sA1 = (uint32_t)(lrow1 * ROWB + q0 * 16);

    // prologue: issue cp.async for chunks 0..2
#pragma unroll
    for (int s = 0; s < NSTAGE - 1; s++) {
        int k0 = s * 32;
        uint32_t ab = smb + s * 2 * STAGEB;
        uint32_t bb = ab + STAGEB;
        cpa16(ab + sA0, pa_base + (size_t)lrow0 * DDIM + k0 + q0 * 8);
        cpa16(ab + sA1, pa_base + (size_t)lrow1 * DDIM + k0 + q0 * 8);
        cpa16(bb + sA0, pb_base + (size_t)lrow0 * DDIM + k0 + q0 * 8);
        cpa16(bb + sA1, pb_base + (size_t)lrow1 * DDIM + k0 + q0 * 8);
        cpa_commit();
    }

    // per-tile mask packing into smem (LDG latency overlaps cp.async drain)
    {
        int mode = g_mask_mode;
        pack_rect(mraw, mode, bi * BM, bj * BM, mrow, tid);
        if (!diag) pack_rect(mraw, mode, bj * BM, bi * BM, mcol, tid);
    }

    // ldmatrix per-lane byte offsets
    const uint32_t aoff = (uint32_t)((wr * 32 + (lane & 15)) * ROWB + (lane >> 4) * 16);
    const uint32_t boff = (uint32_t)((wc * 64 + ((lane >> 4) & 1) * 8 + (lane & 7)) * ROWB
                                     + ((lane >> 3) & 1) * 16);

    float acc[2][8][4];
#pragma unroll
    for (int i = 0; i < 2; i++)
#pragma unroll
        for (int j = 0; j < 8; j++)
#pragma unroll
            for (int r = 0; r < 4; r++) acc[i][j][r] = 0.f;

    for (int c = 0; c < NCHUNK; c++) {
        cpa_wait<NSTAGE - 2>();   // stage c arrived
        __syncthreads();          // + all threads done computing stage c-1

        if (c + NSTAGE - 1 < NCHUNK) {
            int k0 = (c + NSTAGE - 1) * 32;
            int s  = (c + NSTAGE - 1) & (NSTAGE - 1);
            uint32_t ab = smb + s * 2 * STAGEB;
            uint32_t bb = ab + STAGEB;
            cpa16(ab + sA0, pa_base + (size_t)lrow0 * DDIM + k0 + q0 * 8);
            cpa16(ab + sA1, pa_base + (size_t)lrow1 * DDIM + k0 + q0 * 8);
            cpa16(bb + sA0, pb_base + (size_t)lrow0 * DDIM + k0 + q0 * 8);
            cpa16(bb + sA1, pb_base + (size_t)lrow1 * DDIM + k0 + q0 * 8);
        }
        cpa_commit();

        const uint32_t aB = smb + (c & (NSTAGE - 1)) * 2 * STAGEB + aoff;
        const uint32_t bB = aB - aoff + STAGEB + boff;
#pragma unroll
        for (int ks = 0; ks < 2; ks++) {
            uint32_t afr[2][4];
            ldmx4(afr[0], aB + ks * 32);
            ldmx4(afr[1], aB + 16 * ROWB + ks * 32);
            uint32_t bfr[8][2];
#pragma unroll
            for (int fp = 0; fp < 4; fp++) {
                uint32_t r4[4];
                ldmx4(r4, bB + fp * 16 * ROWB + ks * 32);
                bfr[fp * 2 + 0][0] = r4[0]; bfr[fp * 2 + 0][1] = r4[1];
                bfr[fp * 2 + 1][0] = r4[2]; bfr[fp * 2 + 1][1] = r4[3];
            }
#pragma unroll
            for (int fm = 0; fm < 2; fm++)
#pragma unroll
                for (int fn = 0; fn < 8; fn++)
                    mma16816(acc[fm][fn], afr[fm], bfr[fn]);
        }
    }
    __syncthreads();   // mask pack + all MMA consumption done

    // ------------------------------ epilogue -------------------------------
    const int lq = lane >> 2;       // 0..7
    const int lr = lane & 3;        // 0..3
    const uint32_t* colm = diag ? mrow : mcol;

    float x2v[4];
#pragma unroll
    for (int fm = 0; fm < 2; fm++)
#pragma unroll
        for (int hm = 0; hm < 2; hm++)
            x2v[fm * 2 + hm] = sy2a[wr * 32 + fm * 16 + lq + hm * 8];

    float y2v[16];
#pragma unroll
    for (int fn = 0; fn < 8; fn++)
#pragma unroll
        for (int h = 0; h < 2; h++)
            y2v[fn * 2 + h] = sy2b[wc * 64 + fn * 8 + 2 * lr + h];

    uint32_t rw[8];
#pragma unroll
    for (int fm = 0; fm < 2; fm++)
#pragma unroll
        for (int hm = 0; hm < 2; hm++) {
            int mloc = wr * 32 + fm * 16 + lq + hm * 8;
#pragma unroll
            for (int k = 0; k < 2; k++)
                rw[(fm * 2 + hm) * 2 + k] = mrow[mloc * 4 + wc * 2 + k];
        }

    uint32_t cw[16];
#pragma unroll
    for (int fn = 0; fn < 8; fn++)
#pragma unroll
        for (int h = 0; h < 2; h++) {
            int nloc = wc * 64 + fn * 8 + 2 * lr + h;
            cw[fn * 2 + h] = colm[nloc * 4 + wr];
        }

    float rowp[4] = {0.f, 0.f, 0.f, 0.f};
    float colp[16];
#pragma unroll
    for (int i = 0; i < 16; i++) colp[i] = 0.f;

#pragma unroll
    for (int fm = 0; fm < 2; fm++)
#pragma unroll
        for (int fn = 0; fn < 8; fn++)
#pragma unroll
            for (int r = 0; r < 4; r++) {
                int hm = r >> 1, h = r & 1;
                int mloc = wr * 32 + fm * 16 + lq + hm * 8;
                int nloc = wc * 64 + fn * 8 + 2 * lr + h;
                float sq = x2v[fm * 2 + hm] + y2v[fn * 2 + h] - 2.f * acc[fm][fn][r];
                float dd = fast_dist(fmaxf(sq, 0.f) + 1e-12f);
                if (diag && mloc == nloc) dd = 1e-6f;   // exact self-distance
                if (ap_tile && mloc == nloc) g_ap[bj * BM + mloc] = dd;
                float ev = fast_expm(dd);
                int nn = fn * 8 + 2 * lr + h;           // 0..63 within wc half
                if ((rw[(fm * 2 + hm) * 2 + (nn >> 5)] >> (nn & 31)) & 1u)
                    rowp[fm * 2 + hm] += ev;
                if ((cw[fn * 2 + h] >> (fm * 16 + lq + hm * 8)) & 1u)
                    colp[fn * 2 + h] += ev;
            }

    // row partials: reduce over the 4-lane quad
#pragma unroll
    for (int i = 0; i < 4; i++) {
        rowp[i] += __shfl_xor_sync(0xffffffffu, rowp[i], 1);
        rowp[i] += __shfl_xor_sync(0xffffffffu, rowp[i], 2);
    }
    if (lr == 0) {
#pragma unroll
        for (int fm = 0; fm < 2; fm++)
#pragma unroll
            for (int hm = 0; hm < 2; hm++)
                rowred[wr * 32 + fm * 16 + lq + hm * 8][wc] = rowp[fm * 2 + hm];
    }

    // col partials: reduce over lq (xor 4, 8, 16)
#pragma unroll
    for (int i = 0; i < 16; i++) {
        colp[i] += __shfl_xor_sync(0xffffffffu, colp[i], 4);
        colp[i] += __shfl_xor_sync(0xffffffffu, colp[i], 8);
        colp[i] += __shfl_xor_sync(0xffffffffu, colp[i], 16);
    }
    if (lane < 4) {
#pragma unroll
        for (int fn = 0; fn < 8; fn++)
#pragma unroll
            for (int h = 0; h < 2; h++)
                colred[wc * 64 + fn * 8 + 2 * lane + h][wr] = colp[fn * 2 + h];
    }
    __syncthreads();

    if (tid < BM) {
        g_partial[(size_t)bj * TWO_N + bi * BM + tid] = rowred[tid][0] + rowred[tid][1];
        if (!diag)
            g_partial[(size_t)bi * TWO_N + bj * BM + tid] =
                colred[tid][0] + colred[tid][1] + colred[tid][2] + colred[tid][3];
    }
}

// ------------------------- fused loss reduction (single launch) -------------
// 32 blocks x 128 threads; last-done block folds the 32 partials.
__global__ void loss_kernel(float* __restrict__ out) {
    __shared__ float ssum[128];
    __shared__ int   scnt[128];
    __shared__ int   s_last;
    int tid = threadIdx.x;
    int i   = blockIdx.x * 128 + tid;          // anchor index 0..4095

    float rs = 0.f;
#pragma unroll
    for (int c = 0; c < NBJ; c++) rs += g_partial[(size_t)c * TWO_N + i];
    float rs2 = 0.f;
#pragma unroll
    for (int c = 0; c < NBJ; c++) rs2 += g_partial[(size_t)c * TWO_N + i + NHALF];
    rs += rs2;

    float j = logf(rs) + g_ap[i];
    float s = 0.f;
    int   cnt = 0;
    if (!isnan(j)) {
        cnt = 1;
        float tt = fmaxf(j, 0.f);
        s = tt * tt;
    }
    ssum[tid] = s;
    scnt[tid] = cnt;
    __syncthreads();
    for (int o = 64; o > 0; o >>= 1) {
        if (tid < o) { ssum[tid] += ssum[tid + o]; scnt[tid] += scnt[tid + o]; }
        __syncthreads();
    }
    if (tid == 0) {
        g_bsum[blockIdx.x] = ssum[0];
        g_bcnt[blockIdx.x] = scnt[0];
        __threadfence();
        int prev = atomicAdd(&g_done, 1);
        s_last = (prev == NBLK1 - 1) ? 1 : 0;
    }
    __syncthreads();
    if (s_last && tid < 32) {
        __threadfence();                       // make peer writes visible
        float fs = g_bsum[tid];
        int   fc = g_bcnt[tid];
#pragma unroll
        for (int o = 16; o > 0; o >>= 1) {
            fs += __shfl_xor_sync(0xffffffffu, fs, o);
            fc += __shfl_xor_sync(0xffffffffu, fc, o);
        }
        if (tid == 0) {
            float cntf = fmaxf((float)fc, 1.f);
            out[0] = fs / cntf * 0.5f;
            g_done = 0;                        // reset for next graph replay
        }
    }
}

// ---------------------------------------------------------------------------
extern "C" void kernel_launch(void* const* d_in, const int* in_sizes, int n_in,
                              void* d_out, int out_size) {
    const float* E    = (const float*)d_in[0];
    const void*  mask = d_in[1];
    float*       out  = (float*)d_out;

    prep_kernel<<<(TWO_N * 32) / 256, 256>>>(E, (const unsigned int*)mask);

    cudaFuncSetAttribute(tile_kernel, cudaFuncAttributeMaxDynamicSharedMemorySize,
                         SMEM_TOTAL);
    tile_kernel<<<NTILE, 256, SMEM_TOTAL>>>(mask);

    loss_kernel<<<NBLK1, 128>>>(out);
}